// round 1
// baseline (speedup 1.0000x reference)
#include <cuda_runtime.h>

#define BATCH 8
#define C 64
#define H 224
#define W 224
#define E 768
#define PH 56
#define PW 56
#define HW (H*W)        // 50176
#define NPB (PH*PW)     // 3136 patches per batch
#define NP (BATCH*NPB)  // 25088 total patches
#define KDIM 1024       // C * 4 * 4

// ---------------- scratch (device globals: allocation-free) ----------------
__device__ float g_tokens[BATCH * HW * C];   // NHWC layout: [b][h][w][c]
__device__ float g_V[KDIM * (size_t)NP];     // [k][n] row-major, k = c*16+py*4+px
__device__ float g_params[NP * 4];           // per patch: offx, offy, scx, scy

// ---------------------------------------------------------------------------
// Stage 1: per-patch avg-pool + leaky-relu + 1x1 convs (offsets & scales)
// One warp per patch. Lanes 0-15 = pixels (half 0), lanes 16-31 = pixels (half 1).
// Each half handles alternating channels; reduce over 16 pixel-lanes via shfl.
// ---------------------------------------------------------------------------
__global__ void params_kernel(const float* __restrict__ x,
                              const float* __restrict__ w_off,
                              const float* __restrict__ b_off,
                              const float* __restrict__ w_sc,
                              const float* __restrict__ b_sc) {
    int warp = (blockIdx.x * blockDim.x + threadIdx.x) >> 5;
    if (warp >= NP) return;
    int lane = threadIdx.x & 31;
    int n = warp;
    int b = n / NPB; int r = n - b * NPB;
    int i = r / PW;  int j = r - i * PW;
    int pix = lane & 15, half = lane >> 4;
    int py = pix >> 2, px = pix & 3;
    int h0 = i * 4 + py, w0 = j * 4 + px;
    const float* xb = x + ((size_t)b * C) * HW + h0 * W + w0;

    float aox = 0.f, aoy = 0.f, asx = 0.f, asy = 0.f;
    #pragma unroll 4
    for (int it = 0; it < 32; ++it) {
        int c = it * 2 + half;
        float v = xb[(size_t)c * HW];
        // sum over the 16 pixels (lanes within each half)
        v += __shfl_xor_sync(0xffffffffu, v, 1);
        v += __shfl_xor_sync(0xffffffffu, v, 2);
        v += __shfl_xor_sync(0xffffffffu, v, 4);
        v += __shfl_xor_sync(0xffffffffu, v, 8);
        float g = v * (1.0f / 16.0f);
        g = (g > 0.f) ? g : 0.01f * g;          // leaky relu 0.01
        aox += g * w_off[c];
        aoy += g * w_off[C + c];
        asx += g * w_sc[c];
        asy += g * w_sc[C + c];
    }
    // combine the two channel-halves
    aox += __shfl_xor_sync(0xffffffffu, aox, 16);
    aoy += __shfl_xor_sync(0xffffffffu, aoy, 16);
    asx += __shfl_xor_sync(0xffffffffu, asx, 16);
    asy += __shfl_xor_sync(0xffffffffu, asy, 16);
    if (lane == 0) {
        g_params[n * 4 + 0] = (aox + b_off[0]) * (1.0f / 56.0f);  // offs / (W//p)
        g_params[n * 4 + 1] = (aoy + b_off[1]) * (1.0f / 56.0f);  // offs / (H//p)
        g_params[n * 4 + 2] = asx + b_sc[0];
        g_params[n * 4 + 3] = asy + b_sc[1];
    }
}

// ---------------------------------------------------------------------------
// Stage 2: tokens = 1x1 conv (64->64) + bias, output stored NHWC.
// Block = 256 threads, 64-pixel tile of one batch image.
// ---------------------------------------------------------------------------
__global__ void tokens_kernel(const float* __restrict__ x,
                              const float* __restrict__ w1,
                              const float* __restrict__ b1) {
    __shared__ float w1s[C * C];     // [c][k]
    __shared__ float Xs[C * 64];     // [k][px]
    int b = blockIdx.y;
    int p0 = blockIdx.x * 64;
    int tid = threadIdx.x;

    for (int idx = tid; idx < C * C; idx += 256) w1s[idx] = w1[idx];
    for (int idx = tid; idx < C * 64; idx += 256) {
        int k = idx >> 6, px = idx & 63;
        Xs[idx] = x[((size_t)b * C + k) * HW + p0 + px];
    }
    __syncthreads();

    int c = tid >> 2;
    int pxb = (tid & 3) * 16;
    float acc[16];
    float bias = b1[c];
    #pragma unroll
    for (int q = 0; q < 16; ++q) acc[q] = bias;

    #pragma unroll 8
    for (int k = 0; k < C; ++k) {
        float wv = w1s[c * C + k];
        const float* xr = &Xs[k * 64 + pxb];
        #pragma unroll
        for (int q = 0; q < 16; ++q) acc[q] += wv * xr[q];
    }

    float* outp = g_tokens + ((size_t)b * HW + p0 + pxb) * C + c;
    #pragma unroll
    for (int q = 0; q < 16; ++q) outp[q * C] = acc[q];
}

// ---------------------------------------------------------------------------
// Stage 3: grid computation + bilinear gather into V[k][n] (GEMM B-matrix).
// Block = 256 threads = 8 patches x 16 pixels x 2 channel-halves.
// tokens are NHWC so each corner read is 128B contiguous per thread.
// ---------------------------------------------------------------------------
__global__ void gather_kernel() {
    __shared__ float sv[8 * 1032];   // [patch][k], padded stride to kill bank conflicts
    int n0 = blockIdx.x * 8;
    int tid = threadIdx.x;
    int slot = tid >> 1, half = tid & 1;
    int pl = slot >> 4, pix = slot & 15;
    int n = n0 + pl;
    int b = n / NPB; int r = n - b * NPB;
    int i = r / PW;  int j = r - i * PW;

    float offx = g_params[n * 4 + 0];
    float offy = g_params[n * 4 + 1];
    float scx  = g_params[n * 4 + 2];
    float scy  = g_params[n * 4 + 3];

    int py = pix >> 2, px = pix & 3;
    const float inv223 = 1.0f / 223.0f;
    float gx = (-1.0f + 2.0f * (4 * j + 1.5f) * inv223)
             + ((px - 1.5f) * 2.0f * inv223) * (1.0f + scx) + offx;
    float gy = (-1.0f + 2.0f * (4 * i + 1.5f) * inv223)
             + ((py - 1.5f) * 2.0f * inv223) * (1.0f + scy) + offy;
    float ix = (gx + 1.0f) * 0.5f * 223.0f;   // align_corners=True
    float iy = (gy + 1.0f) * 0.5f * 223.0f;

    float x0f = floorf(ix), y0f = floorf(iy);
    int x0 = (int)x0f, y0 = (int)y0f;
    float wx1 = ix - x0f, wx0 = 1.f - wx1;
    float wy1 = iy - y0f, wy0 = 1.f - wy1;

    float acc[32];
    #pragma unroll
    for (int q = 0; q < 32; ++q) acc[q] = 0.f;

    const float* tb = g_tokens + ((size_t)b * HW) * C + half * 32;
    int   xs[4] = { x0, x0 + 1, x0,     x0 + 1 };
    int   ys[4] = { y0, y0,     y0 + 1, y0 + 1 };
    float ws[4] = { wx0 * wy0, wx1 * wy0, wx0 * wy1, wx1 * wy1 };

    #pragma unroll
    for (int cr = 0; cr < 4; ++cr) {
        int xc = xs[cr], yc = ys[cr];
        if ((unsigned)xc < (unsigned)W && (unsigned)yc < (unsigned)H) {
            float wgt = ws[cr];
            const float4* p4 = (const float4*)(tb + ((size_t)yc * W + xc) * C);
            #pragma unroll
            for (int q = 0; q < 8; ++q) {
                float4 t = p4[q];
                acc[q * 4 + 0] += wgt * t.x;
                acc[q * 4 + 1] += wgt * t.y;
                acc[q * 4 + 2] += wgt * t.z;
                acc[q * 4 + 3] += wgt * t.w;
            }
        }
    }

    #pragma unroll
    for (int q = 0; q < 32; ++q) {
        int c = half * 32 + q;
        sv[pl * 1032 + c * 16 + pix] = acc[q];   // k = c*16 + py*4 + px
    }
    __syncthreads();

    // coalesced write-out: 8 consecutive n per k (32B sectors, aligned)
    for (int idx = tid; idx < 8192; idx += 256) {
        int k = idx >> 3, plw = idx & 7;
        g_V[(size_t)k * NP + n0 + plw] = sv[plw * 1032 + k];
    }
}

// ---------------------------------------------------------------------------
// Stage 4: SGEMM  out(768 x 25088) = W2(768 x 1024) * V(1024 x 25088) + bias
// 128x128 tile, BK=8, 8x8 per-thread microtile, 256 threads.
// All dims divide exactly -> no bounds checks.
// ---------------------------------------------------------------------------
__global__ void gemm_kernel(const float* __restrict__ w2,
                            const float* __restrict__ b2,
                            float* __restrict__ out) {
    __shared__ float As[8][128];
    __shared__ float Bs[8][128];
    int tid = threadIdx.x;
    int m0 = blockIdx.y * 128;
    int n0 = blockIdx.x * 128;
    int tx = tid & 15, ty = tid >> 4;

    float acc[8][8];
    #pragma unroll
    for (int a = 0; a < 8; ++a)
        #pragma unroll
        for (int bq = 0; bq < 8; ++bq) acc[a][bq] = 0.f;

    int ar = tid >> 1;          // A row within tile (0..127)
    int ac = (tid & 1) * 4;     // A k-offset (0 or 4)
    int br = tid >> 5;          // B k-row (0..7)
    int bc = (tid & 31) * 4;    // B col offset (0..124)

    for (int kt = 0; kt < KDIM / 8; ++kt) {
        float4 av = *(const float4*)&w2[(size_t)(m0 + ar) * KDIM + kt * 8 + ac];
        float4 bv = *(const float4*)&g_V[(size_t)(kt * 8 + br) * NP + n0 + bc];
        As[ac + 0][ar] = av.x;
        As[ac + 1][ar] = av.y;
        As[ac + 2][ar] = av.z;
        As[ac + 3][ar] = av.w;
        *(float4*)&Bs[br][bc] = bv;
        __syncthreads();
        #pragma unroll
        for (int k = 0; k < 8; ++k) {
            float a[8], bb[8];
            #pragma unroll
            for (int q = 0; q < 8; ++q) a[q]  = As[k][ty * 8 + q];
            #pragma unroll
            for (int q = 0; q < 8; ++q) bb[q] = Bs[k][tx * 8 + q];
            #pragma unroll
            for (int q = 0; q < 8; ++q)
                #pragma unroll
                for (int p = 0; p < 8; ++p) acc[q][p] += a[q] * bb[p];
        }
        __syncthreads();
    }

    #pragma unroll
    for (int q = 0; q < 8; ++q) {
        int m = m0 + ty * 8 + q;
        float bias = b2[m];
        #pragma unroll
        for (int p = 0; p < 8; ++p) {
            int n = n0 + tx * 8 + p;
            int bb = n / NPB;
            int rr = n - bb * NPB;
            // out[b][e][i][j] : b*E*NPB + e*NPB + (i*56+j)
            out[(size_t)bb * (E * NPB) + (size_t)m * NPB + rr] = acc[q][p] + bias;
        }
    }
}

// ---------------------------------------------------------------------------
extern "C" void kernel_launch(void* const* d_in, const int* in_sizes, int n_in,
                              void* d_out, int out_size) {
    const float* x     = (const float*)d_in[0];
    const float* w1    = (const float*)d_in[1];
    const float* b1    = (const float*)d_in[2];
    const float* w2    = (const float*)d_in[3];
    const float* b2    = (const float*)d_in[4];
    const float* w_off = (const float*)d_in[5];
    const float* b_off = (const float*)d_in[6];
    const float* w_sc  = (const float*)d_in[7];
    const float* b_sc  = (const float*)d_in[8];
    float* out = (float*)d_out;

    params_kernel<<<NP / 8, 256>>>(x, w_off, b_off, w_sc, b_sc);
    tokens_kernel<<<dim3(HW / 64, BATCH), 256>>>(x, w1, b1);
    gather_kernel<<<NP / 8, 256>>>();
    gemm_kernel<<<dim3(NP / 128, E / 128), 256>>>(w2, b2, out);
}

// round 3
// speedup vs baseline: 1.5582x; 1.5582x over previous
#include <cuda_runtime.h>
#include <cuda_bf16.h>
#include <cstdint>

#define BATCH 8
#define C 64
#define H 224
#define W 224
#define E 768
#define PH 56
#define PW 56
#define HW (H*W)        // 50176
#define NPB (PH*PW)     // 3136 patches per batch
#define NP (BATCH*NPB)  // 25088 total patches
#define KDIM 1024       // C * 4 * 4

// ---------------- scratch (device globals: allocation-free) ----------------
__device__ float g_tokens[BATCH * HW * C];                 // NHWC [b][h][w][c]
__device__ __nv_bfloat16 g_Vh[(size_t)NP * KDIM];          // [n][k] hi
__device__ __nv_bfloat16 g_Vl[(size_t)NP * KDIM];          // [n][k] lo
__device__ __nv_bfloat16 g_W2h[E * KDIM];                  // [m][k] hi
__device__ __nv_bfloat16 g_W2l[E * KDIM];                  // [m][k] lo
__device__ float g_params[NP * 4];                         // offx, offy, scx, scy

// ======================= PTX helpers (sm_100 base ISA only) ================
__device__ __forceinline__ uint32_t smem_u32(const void* p) {
    uint32_t a;
    asm("{ .reg .u64 t; cvta.to.shared.u64 t, %1; cvt.u32.u64 %0, t; }" : "=r"(a) : "l"(p));
    return a;
}
#define CP_ASYNC16(dst, src) \
    asm volatile("cp.async.cg.shared.global [%0], [%1], 16;" :: "r"(dst), "l"(src) : "memory")
#define CP_COMMIT() asm volatile("cp.async.commit_group;" ::: "memory")
#define CP_WAIT(n)  asm volatile("cp.async.wait_group %0;" :: "n"(n) : "memory")

#define LDSM_X4(r0, r1, r2, r3, addr) \
    asm volatile("ldmatrix.sync.aligned.m8n8.x4.shared.b16 {%0,%1,%2,%3}, [%4];" \
        : "=r"(r0), "=r"(r1), "=r"(r2), "=r"(r3) : "r"(addr))

#define MMA16816(d, a, b) \
    asm volatile("mma.sync.aligned.m16n8k16.row.col.f32.bf16.bf16.f32 " \
        "{%0,%1,%2,%3}, {%4,%5,%6,%7}, {%8,%9}, {%0,%1,%2,%3};" \
        : "+f"((d)[0]), "+f"((d)[1]), "+f"((d)[2]), "+f"((d)[3]) \
        : "r"((a)[0]), "r"((a)[1]), "r"((a)[2]), "r"((a)[3]), \
          "r"((b)[0]), "r"((b)[1]))

// ---------------------------------------------------------------------------
// Stage 0: split w2 into bf16 hi/lo
// ---------------------------------------------------------------------------
__global__ void w2split_kernel(const float* __restrict__ w2) {
    int i = blockIdx.x * 256 + threadIdx.x;
    if (i >= E * KDIM) return;
    float v = w2[i];
    __nv_bfloat16 h = __float2bfloat16(v);
    g_W2h[i] = h;
    g_W2l[i] = __float2bfloat16(v - __bfloat162float(h));
}

// ---------------------------------------------------------------------------
// Stage 1: per-patch avg-pool + leaky-relu + 1x1 convs (offsets & scales)
// ---------------------------------------------------------------------------
__global__ void params_kernel(const float* __restrict__ x,
                              const float* __restrict__ w_off,
                              const float* __restrict__ b_off,
                              const float* __restrict__ w_sc,
                              const float* __restrict__ b_sc) {
    int warp = (blockIdx.x * blockDim.x + threadIdx.x) >> 5;
    if (warp >= NP) return;
    int lane = threadIdx.x & 31;
    int n = warp;
    int b = n / NPB; int r = n - b * NPB;
    int i = r / PW;  int j = r - i * PW;
    int pix = lane & 15, half = lane >> 4;
    int py = pix >> 2, px = pix & 3;
    int h0 = i * 4 + py, w0 = j * 4 + px;
    const float* xb = x + ((size_t)b * C) * HW + h0 * W + w0;

    float aox = 0.f, aoy = 0.f, asx = 0.f, asy = 0.f;
    #pragma unroll 4
    for (int it = 0; it < 32; ++it) {
        int c = it * 2 + half;
        float v = xb[(size_t)c * HW];
        v += __shfl_xor_sync(0xffffffffu, v, 1);
        v += __shfl_xor_sync(0xffffffffu, v, 2);
        v += __shfl_xor_sync(0xffffffffu, v, 4);
        v += __shfl_xor_sync(0xffffffffu, v, 8);
        float g = v * (1.0f / 16.0f);
        g = (g > 0.f) ? g : 0.01f * g;
        aox += g * w_off[c];
        aoy += g * w_off[C + c];
        asx += g * w_sc[c];
        asy += g * w_sc[C + c];
    }
    aox += __shfl_xor_sync(0xffffffffu, aox, 16);
    aoy += __shfl_xor_sync(0xffffffffu, aoy, 16);
    asx += __shfl_xor_sync(0xffffffffu, asx, 16);
    asy += __shfl_xor_sync(0xffffffffu, asy, 16);
    if (lane == 0) {
        g_params[n * 4 + 0] = (aox + b_off[0]) * (1.0f / 56.0f);
        g_params[n * 4 + 1] = (aoy + b_off[1]) * (1.0f / 56.0f);
        g_params[n * 4 + 2] = asx + b_sc[0];
        g_params[n * 4 + 3] = asy + b_sc[1];
    }
}

// ---------------------------------------------------------------------------
// Stage 2: tokens = 1x1 conv (64->64) + bias, NHWC output.
// ---------------------------------------------------------------------------
__global__ void tokens_kernel(const float* __restrict__ x,
                              const float* __restrict__ w1,
                              const float* __restrict__ b1) {
    __shared__ float w1s[C * C];
    __shared__ float Xs[C * 64];
    int b = blockIdx.y;
    int p0 = blockIdx.x * 64;
    int tid = threadIdx.x;

    for (int idx = tid; idx < C * C; idx += 256) w1s[idx] = w1[idx];
    for (int idx = tid; idx < C * 64; idx += 256) {
        int k = idx >> 6, px = idx & 63;
        Xs[idx] = x[((size_t)b * C + k) * HW + p0 + px];
    }
    __syncthreads();

    int c = tid >> 2;
    int pxb = (tid & 3) * 16;
    float acc[16];
    float bias = b1[c];
    #pragma unroll
    for (int q = 0; q < 16; ++q) acc[q] = bias;

    #pragma unroll 8
    for (int k = 0; k < C; ++k) {
        float wv = w1s[c * C + k];
        const float* xr = &Xs[k * 64 + pxb];
        #pragma unroll
        for (int q = 0; q < 16; ++q) acc[q] += wv * xr[q];
    }

    float* outp = g_tokens + ((size_t)b * HW + p0 + pxb) * C + c;
    #pragma unroll
    for (int q = 0; q < 16; ++q) outp[q * C] = acc[q];
}

// ---------------------------------------------------------------------------
// Stage 3: grid + bilinear gather -> V rows [n][k] as bf16 hi/lo (GEMM B).
// ---------------------------------------------------------------------------
__global__ void gather_kernel() {
    __shared__ float sv[8 * 1032];
    int n0 = blockIdx.x * 8;
    int tid = threadIdx.x;
    int slot = tid >> 1, half = tid & 1;
    int pl = slot >> 4, pix = slot & 15;
    int n = n0 + pl;
    int b = n / NPB; int r = n - b * NPB;
    int i = r / PW;  int j = r - i * PW;

    float offx = g_params[n * 4 + 0];
    float offy = g_params[n * 4 + 1];
    float scx  = g_params[n * 4 + 2];
    float scy  = g_params[n * 4 + 3];

    int py = pix >> 2, px = pix & 3;
    const float inv223 = 1.0f / 223.0f;
    float gx = (-1.0f + 2.0f * (4 * j + 1.5f) * inv223)
             + ((px - 1.5f) * 2.0f * inv223) * (1.0f + scx) + offx;
    float gy = (-1.0f + 2.0f * (4 * i + 1.5f) * inv223)
             + ((py - 1.5f) * 2.0f * inv223) * (1.0f + scy) + offy;
    float ix = (gx + 1.0f) * 0.5f * 223.0f;
    float iy = (gy + 1.0f) * 0.5f * 223.0f;

    float x0f = floorf(ix), y0f = floorf(iy);
    int x0 = (int)x0f, y0 = (int)y0f;
    float wx1 = ix - x0f, wx0 = 1.f - wx1;
    float wy1 = iy - y0f, wy0 = 1.f - wy1;

    float acc[32];
    #pragma unroll
    for (int q = 0; q < 32; ++q) acc[q] = 0.f;

    const float* tb = g_tokens + ((size_t)b * HW) * C + half * 32;
    int   xs[4] = { x0, x0 + 1, x0,     x0 + 1 };
    int   ys[4] = { y0, y0,     y0 + 1, y0 + 1 };
    float ws[4] = { wx0 * wy0, wx1 * wy0, wx0 * wy1, wx1 * wy1 };

    #pragma unroll
    for (int cr = 0; cr < 4; ++cr) {
        int xc = xs[cr], yc = ys[cr];
        if ((unsigned)xc < (unsigned)W && (unsigned)yc < (unsigned)H) {
            float wgt = ws[cr];
            const float4* p4 = (const float4*)(tb + ((size_t)yc * W + xc) * C);
            #pragma unroll
            for (int q = 0; q < 8; ++q) {
                float4 t = p4[q];
                acc[q * 4 + 0] += wgt * t.x;
                acc[q * 4 + 1] += wgt * t.y;
                acc[q * 4 + 2] += wgt * t.z;
                acc[q * 4 + 3] += wgt * t.w;
            }
        }
    }

    #pragma unroll
    for (int q = 0; q < 32; ++q) {
        int c = half * 32 + q;
        sv[pl * 1032 + c * 16 + pix] = acc[q];   // k = c*16 + py*4 + px
    }
    __syncthreads();

    // write V rows: [n][k] bf16 hi/lo, coalesced along k
    for (int idx = tid; idx < 8 * KDIM; idx += 256) {
        int plw = idx >> 10, k = idx & 1023;
        float v = sv[plw * 1032 + k];
        __nv_bfloat16 h = __float2bfloat16(v);
        size_t o = (size_t)(n0 + plw) * KDIM + k;
        g_Vh[o] = h;
        g_Vl[o] = __float2bfloat16(v - __bfloat162float(h));
    }
}

// ---------------------------------------------------------------------------
// Stage 4: bf16 mma.sync GEMM  out(768 x 25088) = W2(768x1024)*V + b2
// bf16x3 split via fragment reuse: 3 MMAs (AhBh, AhBl, AlBh) per frag pair.
// CTA 256 thr, tile 128x128, BK=32, 3-stage cp.async, padded 80B SMEM rows.
// ---------------------------------------------------------------------------
#define BK 32
#define NCHUNK (KDIM / BK)          // 32
#define ROWB 80                     // 64B data + 16B pad per row
#define BUFB (128 * ROWB)           // 10240 B per operand buffer
#define STAGEB (4 * BUFB)           // Ah, Al, Bh, Bl
#define NSTG 3
#define GEMM_SMEM (NSTG * STAGEB)   // 122880 B

__device__ __forceinline__ void load_chunk(uint32_t stage, int m0, int n0,
                                           int kc, int tid) {
    // per buffer: 128 rows x 4 segs of 16B = 512 ops; 2 per thread
    #pragma unroll
    for (int it = 0; it < 2; ++it) {
        int idx = tid + it * 256;
        int row = idx >> 2, seg = idx & 3;
        uint32_t dst = (uint32_t)(row * ROWB + seg * 16);
        size_t ea = (((size_t)(m0 + row)) << 11) + (size_t)kc * 64 + seg * 16; // bytes
        size_t eb = (((size_t)(n0 + row)) << 11) + (size_t)kc * 64 + seg * 16;
        CP_ASYNC16(stage + 0 * BUFB + dst, (const char*)g_W2h + ea);
        CP_ASYNC16(stage + 1 * BUFB + dst, (const char*)g_W2l + ea);
        CP_ASYNC16(stage + 2 * BUFB + dst, (const char*)g_Vh + eb);
        CP_ASYNC16(stage + 3 * BUFB + dst, (const char*)g_Vl + eb);
    }
}

__global__ void __launch_bounds__(256, 1) gemm_kernel(const float* __restrict__ b2,
                                                      float* __restrict__ out) {
    extern __shared__ char smem[];
    uint32_t sbase = smem_u32(smem);
    int tid = threadIdx.x;
    int wid = tid >> 5, lane = tid & 31;
    int m0 = blockIdx.x * 128;        // 6 m-tiles, fastest (B-tile reuse in L2)
    int n0 = blockIdx.y * 128;        // 196 n-tiles
    int wm = (wid & 1) * 64;          // warp m offset within tile
    int wn = (wid >> 1) * 32;         // warp n offset within tile

    float acc[4][4][4];
    #pragma unroll
    for (int a = 0; a < 4; ++a)
        #pragma unroll
        for (int b = 0; b < 4; ++b)
            #pragma unroll
            for (int d = 0; d < 4; ++d) acc[a][b][d] = 0.f;

    // ldmatrix per-lane address offsets (within a buffer)
    int li = lane >> 3, lr = lane & 7;
    // A: matrices (m0-7,k0-7),(m8-15,k0-7),(m0-7,k8-15),(m8-15,k8-15)
    uint32_t a_off = (uint32_t)((wm + (li & 1) * 8 + lr) * ROWB + (li >> 1) * 16);
    // B: matrices (n0-7,k0-7),(n8-15,k0-7),(n0-7,k8-15),(n8-15,k8-15)
    uint32_t b_off = (uint32_t)((wn + (li & 1) * 8 + lr) * ROWB + (li >> 1) * 16);

    // prologue: chunks 0,1
    load_chunk(sbase + 0 * STAGEB, m0, n0, 0, tid); CP_COMMIT();
    load_chunk(sbase + 1 * STAGEB, m0, n0, 1, tid); CP_COMMIT();

    for (int kt = 0; kt < NCHUNK; ++kt) {
        if (kt == NCHUNK - 1) { CP_WAIT(0); } else { CP_WAIT(1); }
        __syncthreads();

        uint32_t stg = sbase + (uint32_t)(kt % NSTG) * STAGEB;
        #pragma unroll
        for (int ks = 0; ks < 2; ++ks) {
            uint32_t koff = (uint32_t)(ks * 32);   // 16 k-elems = 32 bytes
            uint32_t ah[4][4], al[4][4], bh[4][2], bl[4][2];
            #pragma unroll
            for (int mi = 0; mi < 4; ++mi) {
                uint32_t ad = stg + a_off + koff + (uint32_t)(mi * 16 * ROWB);
                LDSM_X4(ah[mi][0], ah[mi][1], ah[mi][2], ah[mi][3], ad);
                LDSM_X4(al[mi][0], al[mi][1], al[mi][2], al[mi][3], ad + BUFB);
            }
            #pragma unroll
            for (int nh = 0; nh < 2; ++nh) {       // 2 x4 loads -> 4 B frags
                uint32_t bd = stg + 2 * BUFB + b_off + koff
                            + (uint32_t)(nh * 16 * ROWB);
                uint32_t t0, t1, t2, t3;
                LDSM_X4(t0, t1, t2, t3, bd);
                bh[nh * 2 + 0][0] = t0; bh[nh * 2 + 0][1] = t2;
                bh[nh * 2 + 1][0] = t1; bh[nh * 2 + 1][1] = t3;
                LDSM_X4(t0, t1, t2, t3, bd + BUFB);
                bl[nh * 2 + 0][0] = t0; bl[nh * 2 + 0][1] = t2;
                bl[nh * 2 + 1][0] = t1; bl[nh * 2 + 1][1] = t3;
            }
            #pragma unroll
            for (int mi = 0; mi < 4; ++mi)
                #pragma unroll
                for (int ni = 0; ni < 4; ++ni) {
                    MMA16816(acc[mi][ni], ah[mi], bh[ni]);
                    MMA16816(acc[mi][ni], ah[mi], bl[ni]);
                    MMA16816(acc[mi][ni], al[mi], bh[ni]);
                }
        }
        __syncthreads();

        int c = kt + 2;
        if (c < NCHUNK) {
            load_chunk(sbase + (uint32_t)(c % NSTG) * STAGEB, m0, n0, c, tid);
            CP_COMMIT();
        }
    }

    // epilogue: D layout lane l: rows l/4 (+8), cols 2*(l%4) (+1)
    #pragma unroll
    for (int mi = 0; mi < 4; ++mi) {
        #pragma unroll
        for (int hrow = 0; hrow < 2; ++hrow) {
            int m = m0 + wm + mi * 16 + hrow * 8 + (lane >> 2);
            float bias = b2[m];
            #pragma unroll
            for (int ni = 0; ni < 4; ++ni) {
                int n = n0 + wn + ni * 8 + (lane & 3) * 2;
                int bb = n / NPB;
                int rr = n - bb * NPB;
                float2 v;
                v.x = acc[mi][ni][hrow * 2 + 0] + bias;
                v.y = acc[mi][ni][hrow * 2 + 1] + bias;
                *(float2*)&out[(size_t)bb * (E * NPB) + (size_t)m * NPB + rr] = v;
            }
        }
    }
}

// ---------------------------------------------------------------------------
extern "C" void kernel_launch(void* const* d_in, const int* in_sizes, int n_in,
                              void* d_out, int out_size) {
    const float* x     = (const float*)d_in[0];
    const float* w1    = (const float*)d_in[1];
    const float* b1    = (const float*)d_in[2];
    const float* w2    = (const float*)d_in[3];
    const float* b2    = (const float*)d_in[4];
    const float* w_off = (const float*)d_in[5];
    const float* b_off = (const float*)d_in[6];
    const float* w_sc  = (const float*)d_in[7];
    const float* b_sc  = (const float*)d_in[8];
    float* out = (float*)d_out;

    cudaFuncSetAttribute(gemm_kernel, cudaFuncAttributeMaxDynamicSharedMemorySize,
                         GEMM_SMEM);

    w2split_kernel<<<(E * KDIM + 255) / 256, 256>>>(w2);
    params_kernel<<<NP / 8, 256>>>(x, w_off, b_off, w_sc, b_sc);
    tokens_kernel<<<dim3(HW / 64, BATCH), 256>>>(x, w1, b1);
    gather_kernel<<<NP / 8, 256>>>();
    gemm_kernel<<<dim3(E / 128, NP / 128), 256, GEMM_SMEM>>>(b2, out);
}

// round 5
// speedup vs baseline: 3.8691x; 2.4830x over previous
#include <cuda_runtime.h>
#include <cuda_fp16.h>
#include <cstdint>

#define BATCH 8
#define C 64
#define H 224
#define W 224
#define E 768
#define PH 56
#define PW 56
#define HW (H*W)        // 50176
#define NPB (PH*PW)     // 3136 patches per batch
#define NP (BATCH*NPB)  // 25088 total patches
#define KDIM 1024       // C * 4 * 4

// ---------------- scratch (device globals: allocation-free) ----------------
__device__ __half g_tokensH[BATCH * HW * C];        // NHWC fp16 [b][h][w][c]
__device__ __half g_Vf[(size_t)NP * KDIM];          // [n][k] fp16
__device__ __half g_W2f[E * KDIM];                  // [m][k] fp16
__device__ float  g_params[NP * 4];                 // offx, offy, scx, scy

// ======================= PTX helpers (sm_100 base ISA only) ================
__device__ __forceinline__ uint32_t smem_u32(const void* p) {
    uint32_t a;
    asm("{ .reg .u64 t; cvta.to.shared.u64 t, %1; cvt.u32.u64 %0, t; }" : "=r"(a) : "l"(p));
    return a;
}
#define CP_ASYNC16(dst, src) \
    asm volatile("cp.async.cg.shared.global [%0], [%1], 16;" :: "r"(dst), "l"(src) : "memory")
#define CP_COMMIT() asm volatile("cp.async.commit_group;" ::: "memory")
#define CP_WAIT(n)  asm volatile("cp.async.wait_group %0;" :: "n"(n) : "memory")

#define LDSM_X4(r0, r1, r2, r3, addr) \
    asm volatile("ldmatrix.sync.aligned.m8n8.x4.shared.b16 {%0,%1,%2,%3}, [%4];" \
        : "=r"(r0), "=r"(r1), "=r"(r2), "=r"(r3) : "r"(addr))

#define MMA16816(d, a, b) \
    asm volatile("mma.sync.aligned.m16n8k16.row.col.f32.f16.f16.f32 " \
        "{%0,%1,%2,%3}, {%4,%5,%6,%7}, {%8,%9}, {%0,%1,%2,%3};" \
        : "+f"((d)[0]), "+f"((d)[1]), "+f"((d)[2]), "+f"((d)[3]) \
        : "r"((a)[0]), "r"((a)[1]), "r"((a)[2]), "r"((a)[3]), \
          "r"((b)[0]), "r"((b)[1]))

// ---------------------------------------------------------------------------
// Stage 0: convert w2 to fp16
// ---------------------------------------------------------------------------
__global__ void wsplit_kernel(const float* __restrict__ w2) {
    int i = blockIdx.x * 256 + threadIdx.x;
    if (i >= E * KDIM / 2) return;
    float2 v = ((const float2*)w2)[i];
    ((__half2*)g_W2f)[i] = __floats2half2_rn(v.x, v.y);
}

// ---------------------------------------------------------------------------
// Stage 1: per-patch avg-pool + leaky-relu + 1x1 convs (offsets & scales)
// ---------------------------------------------------------------------------
__global__ void params_kernel(const float* __restrict__ x,
                              const float* __restrict__ w_off,
                              const float* __restrict__ b_off,
                              const float* __restrict__ w_sc,
                              const float* __restrict__ b_sc) {
    int warp = (blockIdx.x * blockDim.x + threadIdx.x) >> 5;
    if (warp >= NP) return;
    int lane = threadIdx.x & 31;
    int n = warp;
    int b = n / NPB; int r = n - b * NPB;
    int i = r / PW;  int j = r - i * PW;
    int pix = lane & 15, half = lane >> 4;
    int py = pix >> 2, px = pix & 3;
    int h0 = i * 4 + py, w0 = j * 4 + px;
    const float* xb = x + ((size_t)b * C) * HW + h0 * W + w0;

    float aox = 0.f, aoy = 0.f, asx = 0.f, asy = 0.f;
    #pragma unroll 4
    for (int it = 0; it < 32; ++it) {
        int c = it * 2 + half;
        float v = xb[(size_t)c * HW];
        v += __shfl_xor_sync(0xffffffffu, v, 1);
        v += __shfl_xor_sync(0xffffffffu, v, 2);
        v += __shfl_xor_sync(0xffffffffu, v, 4);
        v += __shfl_xor_sync(0xffffffffu, v, 8);
        float g = v * (1.0f / 16.0f);
        g = (g > 0.f) ? g : 0.01f * g;
        aox += g * w_off[c];
        aoy += g * w_off[C + c];
        asx += g * w_sc[c];
        asy += g * w_sc[C + c];
    }
    aox += __shfl_xor_sync(0xffffffffu, aox, 16);
    aoy += __shfl_xor_sync(0xffffffffu, aoy, 16);
    asx += __shfl_xor_sync(0xffffffffu, asx, 16);
    asy += __shfl_xor_sync(0xffffffffu, asy, 16);
    if (lane == 0) {
        g_params[n * 4 + 0] = (aox + b_off[0]) * (1.0f / 56.0f);
        g_params[n * 4 + 1] = (aoy + b_off[1]) * (1.0f / 56.0f);
        g_params[n * 4 + 2] = asx + b_sc[0];
        g_params[n * 4 + 3] = asy + b_sc[1];
    }
}

// ---------------------------------------------------------------------------
// Stage 2: tokens = 1x1 conv (64->64) + bias, fp16 NHWC output.
// ---------------------------------------------------------------------------
__global__ void tokens_kernel(const float* __restrict__ x,
                              const float* __restrict__ w1,
                              const float* __restrict__ b1) {
    __shared__ float w1s[C * 66];    // [k][c], stride 66 (conflict-free)
    __shared__ float Xs[C * 64];     // [k][px]
    int b = blockIdx.y;
    int p0 = blockIdx.x * 64;
    int tid = threadIdx.x;

    for (int idx = tid; idx < C * C; idx += 256) {
        int c = idx >> 6, k = idx & 63;          // coalesced read of w1[c][k]
        w1s[k * 66 + c] = w1[idx];
    }
    for (int idx = tid; idx < C * 64; idx += 256) {
        int k = idx >> 6, px = idx & 63;
        Xs[idx] = x[((size_t)b * C + k) * HW + p0 + px];
    }
    __syncthreads();

    int c0  = (tid & 31) * 2;
    int pxg = (tid >> 5) * 8;
    float acc0[8], acc1[8];
    float bias0 = b1[c0], bias1 = b1[c0 + 1];
    #pragma unroll
    for (int q = 0; q < 8; ++q) { acc0[q] = bias0; acc1[q] = bias1; }

    #pragma unroll 8
    for (int k = 0; k < C; ++k) {
        float2 wv = *(const float2*)&w1s[k * 66 + c0];
        const float* xr = &Xs[k * 64 + pxg];
        #pragma unroll
        for (int q = 0; q < 8; ++q) {
            float xv = xr[q];
            acc0[q] += wv.x * xv;
            acc1[q] += wv.y * xv;
        }
    }

    __half2* outp = (__half2*)(g_tokensH + ((size_t)b * HW + p0 + pxg) * C + c0);
    #pragma unroll
    for (int q = 0; q < 8; ++q)
        outp[q * (C / 2)] = __floats2half2_rn(acc0[q], acc1[q]);
}

// ---------------------------------------------------------------------------
// Stage 3: grid + bilinear gather (fp16 tokens) -> V rows [n][k] fp16.
// Each thread: 32 channels per corner = 4 x uint4 (64B).
// ---------------------------------------------------------------------------
__global__ void gather_kernel() {
    __shared__ float sv[8 * 1032];
    int n0 = blockIdx.x * 8;
    int tid = threadIdx.x;
    int slot = tid >> 1, half = tid & 1;
    int pl = slot >> 4, pix = slot & 15;
    int n = n0 + pl;
    int b = n / NPB; int r = n - b * NPB;
    int i = r / PW;  int j = r - i * PW;

    float offx = g_params[n * 4 + 0];
    float offy = g_params[n * 4 + 1];
    float scx  = g_params[n * 4 + 2];
    float scy  = g_params[n * 4 + 3];

    int py = pix >> 2, px = pix & 3;
    const float inv223 = 1.0f / 223.0f;
    float gx = (-1.0f + 2.0f * (4 * j + 1.5f) * inv223)
             + ((px - 1.5f) * 2.0f * inv223) * (1.0f + scx) + offx;
    float gy = (-1.0f + 2.0f * (4 * i + 1.5f) * inv223)
             + ((py - 1.5f) * 2.0f * inv223) * (1.0f + scy) + offy;
    float ix = (gx + 1.0f) * 0.5f * 223.0f;
    float iy = (gy + 1.0f) * 0.5f * 223.0f;

    float x0f = floorf(ix), y0f = floorf(iy);
    int x0 = (int)x0f, y0 = (int)y0f;
    float wx1 = ix - x0f, wx0 = 1.f - wx1;
    float wy1 = iy - y0f, wy0 = 1.f - wy1;

    float acc[32];
    #pragma unroll
    for (int q = 0; q < 32; ++q) acc[q] = 0.f;

    const __half* tb = g_tokensH + ((size_t)b * HW) * C + half * 32;
    int   xs[4] = { x0, x0 + 1, x0,     x0 + 1 };
    int   ys[4] = { y0, y0,     y0 + 1, y0 + 1 };
    float ws[4] = { wx0 * wy0, wx1 * wy0, wx0 * wy1, wx1 * wy1 };

    #pragma unroll
    for (int cr = 0; cr < 4; ++cr) {
        int xc = xs[cr], yc = ys[cr];
        if ((unsigned)xc < (unsigned)W && (unsigned)yc < (unsigned)H) {
            float wgt = ws[cr];
            const uint4* p4 = (const uint4*)(tb + ((size_t)yc * W + xc) * C);
            #pragma unroll
            for (int q = 0; q < 4; ++q) {        // 4 x 16B = 32 halfs (all 32 ch)
                uint4 t = p4[q];
                uint32_t wd[4] = { t.x, t.y, t.z, t.w };
                #pragma unroll
                for (int s = 0; s < 4; ++s) {
                    float2 f = __half22float2(*(__half2*)&wd[s]);
                    acc[q * 8 + s * 2 + 0] += wgt * f.x;
                    acc[q * 8 + s * 2 + 1] += wgt * f.y;
                }
            }
        }
    }

    #pragma unroll
    for (int q = 0; q < 32; ++q) {
        int c = half * 32 + q;
        sv[pl * 1032 + c * 16 + pix] = acc[q];   // k = c*16 + py*4 + px
    }
    __syncthreads();

    // write V rows: [n][k] fp16, half2-vectorized, coalesced along k
    for (int idx = tid; idx < 8 * 512; idx += 256) {
        int plw = idx >> 9, kk = (idx & 511) * 2;
        float v0 = sv[plw * 1032 + kk];
        float v1 = sv[plw * 1032 + kk + 1];
        *(__half2*)&g_Vf[(size_t)(n0 + plw) * KDIM + kk] = __floats2half2_rn(v0, v1);
    }
}

// ---------------------------------------------------------------------------
// Stage 4: fp16 mma.sync GEMM  out(768 x 25088) = W2(768x1024)*V + b2
// Single pass, fp32 accum. CTA 256 thr, tile 128x128, BK=32, 4-stage cp.async.
// ---------------------------------------------------------------------------
#define BK 32
#define NCHUNK (KDIM / BK)          // 32
#define ROWB 80                     // 64B data + 16B pad per row
#define BUFB (128 * ROWB)           // 10240 B per operand buffer
#define STAGEB (2 * BUFB)           // A, B
#define NSTG 4
#define GEMM_SMEM (NSTG * STAGEB)   // 81920 B

__device__ __forceinline__ void load_chunk(uint32_t stage, int m0, int n0,
                                           int kc, int tid) {
    #pragma unroll
    for (int it = 0; it < 2; ++it) {
        int idx = tid + it * 256;
        int row = idx >> 2, seg = idx & 3;
        uint32_t dst = (uint32_t)(row * ROWB + seg * 16);
        size_t ea = (((size_t)(m0 + row)) << 11) + (size_t)kc * 64 + seg * 16; // bytes
        size_t eb = (((size_t)(n0 + row)) << 11) + (size_t)kc * 64 + seg * 16;
        CP_ASYNC16(stage + dst,        (const char*)g_W2f + ea);
        CP_ASYNC16(stage + BUFB + dst, (const char*)g_Vf  + eb);
    }
}

__global__ void __launch_bounds__(256, 2) gemm_kernel(const float* __restrict__ b2,
                                                      float* __restrict__ out) {
    extern __shared__ char smem[];
    uint32_t sbase = smem_u32(smem);
    int tid = threadIdx.x;
    int wid = tid >> 5, lane = tid & 31;
    int m0 = blockIdx.x * 128;        // 6 m-tiles fastest (B-tile reuse in L2)
    int n0 = blockIdx.y * 128;        // 196 n-tiles
    int wm = (wid & 1) * 64;
    int wn = (wid >> 1) * 32;

    float acc[4][4][4];
    #pragma unroll
    for (int a = 0; a < 4; ++a)
        #pragma unroll
        for (int b = 0; b < 4; ++b)
            #pragma unroll
            for (int d = 0; d < 4; ++d) acc[a][b][d] = 0.f;

    int li = lane >> 3, lr = lane & 7;
    uint32_t a_off = (uint32_t)((wm + (li & 1) * 8 + lr) * ROWB + (li >> 1) * 16);
    uint32_t b_off = (uint32_t)((wn + (li & 1) * 8 + lr) * ROWB + (li >> 1) * 16);

    // prologue: chunks 0,1,2
    load_chunk(sbase + 0 * STAGEB, m0, n0, 0, tid); CP_COMMIT();
    load_chunk(sbase + 1 * STAGEB, m0, n0, 1, tid); CP_COMMIT();
    load_chunk(sbase + 2 * STAGEB, m0, n0, 2, tid); CP_COMMIT();

    for (int kt = 0; kt < NCHUNK; ++kt) {
        if (kt <= NCHUNK - 3)      { CP_WAIT(2); }
        else if (kt == NCHUNK - 2) { CP_WAIT(1); }
        else                       { CP_WAIT(0); }
        __syncthreads();

        uint32_t stg = sbase + (uint32_t)(kt % NSTG) * STAGEB;
        #pragma unroll
        for (int ks = 0; ks < 2; ++ks) {
            uint32_t koff = (uint32_t)(ks * 32);   // 16 k-elems = 32 bytes
            uint32_t ah[4][4], bh[4][2];
            #pragma unroll
            for (int mi = 0; mi < 4; ++mi) {
                uint32_t ad = stg + a_off + koff + (uint32_t)(mi * 16 * ROWB);
                LDSM_X4(ah[mi][0], ah[mi][1], ah[mi][2], ah[mi][3], ad);
            }
            #pragma unroll
            for (int nh = 0; nh < 2; ++nh) {
                uint32_t bd = stg + BUFB + b_off + koff + (uint32_t)(nh * 16 * ROWB);
                uint32_t t0, t1, t2, t3;
                LDSM_X4(t0, t1, t2, t3, bd);
                bh[nh * 2 + 0][0] = t0; bh[nh * 2 + 0][1] = t2;
                bh[nh * 2 + 1][0] = t1; bh[nh * 2 + 1][1] = t3;
            }
            #pragma unroll
            for (int mi = 0; mi < 4; ++mi)
                #pragma unroll
                for (int ni = 0; ni < 4; ++ni)
                    MMA16816(acc[mi][ni], ah[mi], bh[ni]);
        }
        __syncthreads();

        int c = kt + 3;
        if (c < NCHUNK) {
            load_chunk(sbase + (uint32_t)(c % NSTG) * STAGEB, m0, n0, c, tid);
            CP_COMMIT();
        }
    }

    // epilogue
    #pragma unroll
    for (int mi = 0; mi < 4; ++mi) {
        #pragma unroll
        for (int hrow = 0; hrow < 2; ++hrow) {
            int m = m0 + wm + mi * 16 + hrow * 8 + (lane >> 2);
            float bias = b2[m];
            #pragma unroll
            for (int ni = 0; ni < 4; ++ni) {
                int n = n0 + wn + ni * 8 + (lane & 3) * 2;
                int bb = n / NPB;
                int rr = n - bb * NPB;
                float2 v;
                v.x = acc[mi][ni][hrow * 2 + 0] + bias;
                v.y = acc[mi][ni][hrow * 2 + 1] + bias;
                *(float2*)&out[(size_t)bb * (E * NPB) + (size_t)m * NPB + rr] = v;
            }
        }
    }
}

// ---------------------------------------------------------------------------
extern "C" void kernel_launch(void* const* d_in, const int* in_sizes, int n_in,
                              void* d_out, int out_size) {
    const float* x     = (const float*)d_in[0];
    const float* w1    = (const float*)d_in[1];
    const float* b1    = (const float*)d_in[2];
    const float* w2    = (const float*)d_in[3];
    const float* b2    = (const float*)d_in[4];
    const float* w_off = (const float*)d_in[5];
    const float* b_off = (const float*)d_in[6];
    const float* w_sc  = (const float*)d_in[7];
    const float* b_sc  = (const float*)d_in[8];
    float* out = (float*)d_out;

    cudaFuncSetAttribute(gemm_kernel, cudaFuncAttributeMaxDynamicSharedMemorySize,
                         GEMM_SMEM);

    wsplit_kernel<<<(E * KDIM / 2 + 255) / 256, 256>>>(w2);
    params_kernel<<<NP / 8, 256>>>(x, w_off, b_off, w_sc, b_sc);
    tokens_kernel<<<dim3(HW / 64, BATCH), 256>>>(x, w1, b1);
    gather_kernel<<<NP / 8, 256>>>();
    gemm_kernel<<<dim3(E / 128, NP / 128), 256, GEMM_SMEM>>>(b2, out);
}